// round 1
// baseline (speedup 1.0000x reference)
#include <cuda_runtime.h>
#include <cstdint>

// Problem constants
#define BB   128      // batch
#define IN_  1024
#define OUT_ 1024
#define NS   16       // i-dimension splits
#define LI   (IN_/NS) // 64 i-values per split
#define NB   8        // batches per block
#define NBG  (BB/NB)  // 16 b-groups
#define O4   (OUT_/4) // 256 float4 lanes over OUT

// Scratch (allocation-free rule: __device__ globals)
__device__ float g_sigma[IN_ * OUT_];            // softplus(ro), 4 MB
__device__ float g_partial[NS * BB * OUT_];      // per-split partial sums, 8 MB

// ---------------------------------------------------------------------------
// Kernel 0: sigma = log1p(exp(ro)), precomputed once so the streaming kernel
// never touches MUFU.
// ---------------------------------------------------------------------------
__global__ void sigma_kernel(const float* __restrict__ ro) {
    int idx = blockIdx.x * blockDim.x + threadIdx.x;   // over IN*OUT/4
    float4 r = reinterpret_cast<const float4*>(ro)[idx];
    float4 s;
    s.x = log1pf(__expf(r.x));
    s.y = log1pf(__expf(r.y));
    s.z = log1pf(__expf(r.z));
    s.w = log1pf(__expf(r.w));
    reinterpret_cast<float4*>(g_sigma)[idx] = s;
}

// ---------------------------------------------------------------------------
// Kernel 1: main streaming kernel.
// Block (s, bg): i in [s*LI, (s+1)*LI), batches b in [bg*NB, bg*NB+NB),
// full OUT tile (256 threads x float4). sig/mu loaded once per i and reused
// across NB batches (8x L2 traffic reduction). eps streamed once from DRAM
// with 8 independent LDG.128 per i per thread for MLP.
// ---------------------------------------------------------------------------
__global__ __launch_bounds__(256, 2)
void main_kernel(const float* __restrict__ x,
                 const float* __restrict__ mu,
                 const float* __restrict__ eps) {
    __shared__ float xs[NB][LI];   // 2 KB

    const int s  = blockIdx.x;     // 0..NS-1
    const int bg = blockIdx.y;     // 0..NBG-1
    const int t  = threadIdx.x;    // 0..255 -> o = 4t..4t+3
    const int i0 = s * LI;
    const int b0 = bg * NB;

    // Cooperative load of the x tile: x[b0..b0+NB, i0..i0+LI)
    for (int k = t; k < NB * LI; k += 256) {
        int bb = k / LI;
        int ii = k % LI;
        xs[bb][ii] = x[(size_t)(b0 + bb) * IN_ + i0 + ii];
    }
    __syncthreads();

    float4 acc[NB];
#pragma unroll
    for (int bb = 0; bb < NB; bb++) acc[bb] = make_float4(0.f, 0.f, 0.f, 0.f);

    const float4* sig4 = reinterpret_cast<const float4*>(g_sigma) + (size_t)i0 * O4 + t;
    const float4* mu4  = reinterpret_cast<const float4*>(mu)      + (size_t)i0 * O4 + t;
    const float4* ep4  = reinterpret_cast<const float4*>(eps)
                         + ((size_t)b0 * IN_ + i0) * O4 + t;

#pragma unroll 1
    for (int ii = 0; ii < LI; ii++) {
        const float4 sg = sig4[(size_t)ii * O4];
        const float4 mw = mu4[(size_t)ii * O4];

        // 8 independent DRAM loads, batched for MLP
        float4 ev[NB];
#pragma unroll
        for (int bb = 0; bb < NB; bb++)
            ev[bb] = ep4[((size_t)bb * IN_ + ii) * O4];

#pragma unroll
        for (int bb = 0; bb < NB; bb++) {
            const float xr = xs[bb][ii];
            const float4 e = ev[bb];
            acc[bb].x = fmaf(xr, fmaf(e.x, sg.x, mw.x), acc[bb].x);
            acc[bb].y = fmaf(xr, fmaf(e.y, sg.y, mw.y), acc[bb].y);
            acc[bb].z = fmaf(xr, fmaf(e.z, sg.z, mw.z), acc[bb].z);
            acc[bb].w = fmaf(xr, fmaf(e.w, sg.w, mw.w), acc[bb].w);
        }
    }

    // Deterministic partials: P[s][b][o]
    float4* P = reinterpret_cast<float4*>(g_partial) + (size_t)s * BB * O4 + t;
#pragma unroll
    for (int bb = 0; bb < NB; bb++)
        P[(size_t)(b0 + bb) * O4] = acc[bb];
}

// ---------------------------------------------------------------------------
// Kernel 2: reduce NS partials + bias term.
// out[b,o] = eps_bias[b,o]*softplus(ro_bias[o]) + mu_bias[o] + sum_s P[s][b][o]
// ---------------------------------------------------------------------------
__global__ void reduce_kernel(const float* __restrict__ mu_bias,
                              const float* __restrict__ ro_bias,
                              const float* __restrict__ eps_bias,
                              float* __restrict__ out) {
    int idx = blockIdx.x * blockDim.x + threadIdx.x;   // over B*OUT/4
    int o4  = idx % O4;

    float4 eb = reinterpret_cast<const float4*>(eps_bias)[idx];
    float4 rb = reinterpret_cast<const float4*>(ro_bias)[o4];
    float4 mb = reinterpret_cast<const float4*>(mu_bias)[o4];

    float4 acc;
    acc.x = fmaf(eb.x, log1pf(__expf(rb.x)), mb.x);
    acc.y = fmaf(eb.y, log1pf(__expf(rb.y)), mb.y);
    acc.z = fmaf(eb.z, log1pf(__expf(rb.z)), mb.z);
    acc.w = fmaf(eb.w, log1pf(__expf(rb.w)), mb.w);

#pragma unroll
    for (int s = 0; s < NS; s++) {
        float4 p = reinterpret_cast<const float4*>(g_partial)[(size_t)s * BB * O4 + idx];
        acc.x += p.x; acc.y += p.y; acc.z += p.z; acc.w += p.w;
    }
    reinterpret_cast<float4*>(out)[idx] = acc;
}

// ---------------------------------------------------------------------------
// Launch. Input order (metadata): x, mu, ro, mu_bias, ro_bias, eps, eps_bias
// ---------------------------------------------------------------------------
extern "C" void kernel_launch(void* const* d_in, const int* in_sizes, int n_in,
                              void* d_out, int out_size) {
    const float* x        = (const float*)d_in[0];
    const float* mu       = (const float*)d_in[1];
    const float* ro       = (const float*)d_in[2];
    const float* mu_bias  = (const float*)d_in[3];
    const float* ro_bias  = (const float*)d_in[4];
    const float* eps      = (const float*)d_in[5];
    const float* eps_bias = (const float*)d_in[6];
    float* out = (float*)d_out;

    // K0: sigma precompute (IN*OUT/4 = 262144 lanes)
    sigma_kernel<<<(IN_ * OUT_ / 4) / 256, 256>>>(ro);

    // K1: main streaming kernel, grid = NS x NBG = 256 blocks, single wave
    dim3 grid(NS, NBG);
    main_kernel<<<grid, 256>>>(x, mu, eps);

    // K2: reduce + bias (B*OUT/4 = 32768 lanes)
    reduce_kernel<<<(BB * OUT_ / 4) / 256, 256>>>(mu_bias, ro_bias, eps_bias, out);
}